// round 1
// baseline (speedup 1.0000x reference)
#include <cuda_runtime.h>
#include <cuda_bf16.h>
#include <math.h>

// Problem constants
#define B_SZ   8192
#define XCOLS  145     // IN_F + LAT + 1
#define IN_F   16
#define LAT    128
#define HID    1024
#define CS     6540    // (M+2)*K
#define MK     6528    // M*K
#define KF     6       // K (fourier terms)

// ---------------- scratch (static device globals; no allocation) ------------
__device__ float g_h1[(size_t)B_SZ * HID];     // 33.5 MB
__device__ float g_h2[(size_t)B_SZ * CS];      // 214 MB
__device__ float g_cc[(size_t)B_SZ * MK];      // 214 MB (v-scaled coeffs)
__device__ float g_v [(size_t)B_SZ * KF];

// ---------------- generic tiled SGEMM: C = epilogue(A@B + bias) -------------
// mode 0: +bias ; mode 1: tanh(+bias) ; mode 2: (+bias) * v[row, col%6]
#define BM 128
#define BN 128
#define BK 16
#define TM 8
#define TN 8

__global__ __launch_bounds__(256, 2)
void sgemm_k(const float* __restrict__ A, int lda,
             const float* __restrict__ Bm, int ldb,
             const float* __restrict__ bias,
             const float* __restrict__ vsc,
             float* __restrict__ C, int ldc,
             int Ndim, int Kdim, int mode)
{
    __shared__ float As[BK][BM + 4];
    __shared__ float Bs[BK][BN + 4];

    const int tid = threadIdx.x;
    const int bm  = blockIdx.y * BM;
    const int bn  = blockIdx.x * BN;
    const int tx  = tid % 16;           // 16 col groups
    const int ty  = tid / 16;           // 16 row groups

    float acc[TM][TN];
    #pragma unroll
    for (int i = 0; i < TM; ++i)
        #pragma unroll
        for (int j = 0; j < TN; ++j) acc[i][j] = 0.f;

    for (int k0 = 0; k0 < Kdim; k0 += BK) {
        // load A tile (BM x BK), consecutive tids -> consecutive k
        #pragma unroll
        for (int i = 0; i < (BM * BK) / 256; ++i) {
            int idx = tid + i * 256;
            int m = idx / BK, k = idx % BK;
            float val = 0.f;
            if (k0 + k < Kdim)
                val = A[(size_t)(bm + m) * lda + k0 + k];
            As[k][m] = val;
        }
        // load B tile (BK x BN), fully coalesced in n
        #pragma unroll
        for (int i = 0; i < (BK * BN) / 256; ++i) {
            int idx = tid + i * 256;
            int k = idx / BN, n = idx % BN;
            float val = 0.f;
            if (k0 + k < Kdim && bn + n < Ndim)
                val = Bm[(size_t)(k0 + k) * ldb + bn + n];
            Bs[k][n] = val;
        }
        __syncthreads();

        #pragma unroll
        for (int k = 0; k < BK; ++k) {
            float ra[TM], rb[TN];
            float4 a0 = *reinterpret_cast<const float4*>(&As[k][ty * TM]);
            float4 a1 = *reinterpret_cast<const float4*>(&As[k][ty * TM + 4]);
            float4 b0 = *reinterpret_cast<const float4*>(&Bs[k][tx * TN]);
            float4 b1 = *reinterpret_cast<const float4*>(&Bs[k][tx * TN + 4]);
            ra[0]=a0.x; ra[1]=a0.y; ra[2]=a0.z; ra[3]=a0.w;
            ra[4]=a1.x; ra[5]=a1.y; ra[6]=a1.z; ra[7]=a1.w;
            rb[0]=b0.x; rb[1]=b0.y; rb[2]=b0.z; rb[3]=b0.w;
            rb[4]=b1.x; rb[5]=b1.y; rb[6]=b1.z; rb[7]=b1.w;
            #pragma unroll
            for (int i = 0; i < TM; ++i)
                #pragma unroll
                for (int j = 0; j < TN; ++j)
                    acc[i][j] = fmaf(ra[i], rb[j], acc[i][j]);
        }
        __syncthreads();
    }

    #pragma unroll
    for (int i = 0; i < TM; ++i) {
        int row = bm + ty * TM + i;
        #pragma unroll
        for (int j = 0; j < TN; ++j) {
            int col = bn + tx * TN + j;
            if (col < Ndim) {
                float val = acc[i][j] + bias[col];
                if (mode == 1)      val = tanhf(val);
                else if (mode == 2) val *= vsc[(size_t)row * KF + (col % KF)];
                C[(size_t)row * ldc + col] = val;
            }
        }
    }
}

// -------- tail: d[j] = h2[b]·W3[:,6528+j] + b3[6528+j]  ->  v[b,0..5] --------
__global__ __launch_bounds__(128)
void tail_v_kernel(const float* __restrict__ h2,
                   const float* __restrict__ W3,
                   const float* __restrict__ b3,
                   const float* __restrict__ x,
                   float* __restrict__ v)
{
    const int b = blockIdx.x;
    const int t = threadIdx.x;  // 128
    float p[12];
    #pragma unroll
    for (int j = 0; j < 12; ++j) p[j] = 0.f;

    const float* hrow = h2 + (size_t)b * CS;
    for (int c = t; c < CS; c += 128) {
        float hv = hrow[c];
        const float* wr = W3 + (size_t)c * CS + MK;
        #pragma unroll
        for (int j = 0; j < 12; ++j) p[j] = fmaf(hv, wr[j], p[j]);
    }

    __shared__ float red[128];
    __shared__ float dtail[12];
    for (int j = 0; j < 12; ++j) {
        red[t] = p[j];
        __syncthreads();
        for (int s = 64; s > 0; s >>= 1) {
            if (t < s) red[t] += red[t + s];
            __syncthreads();
        }
        if (t == 0) dtail[j] = red[0] + b3[MK + j];
        __syncthreads();
    }

    if (t < 6) {
        float s  = x[(size_t)(B_SZ - 1) * XCOLS + IN_F];  // scalar from input
        float sv = fmaf(s, dtail[t], dtail[t + 6]);
        float r  = (t < 3) ? cosf(sv * (float)t) : sinf(sv * (float)(t - 3));
        v[(size_t)b * KF + t] = r;
    }
}

// -------- final: out[b,o] = sum_i inp[b,i]*sum6(cc[(i*64+o)*6..]) + sum6(cc[(1024+o)*6..])
__global__ __launch_bounds__(256)
void final_kernel(const float* __restrict__ cc,
                  const float* __restrict__ x,
                  float* __restrict__ out)
{
    const int b = blockIdx.x;
    const int t = threadIdx.x;  // 256
    __shared__ float row[MK];
    __shared__ float inp[IN_F];

    const float* src = cc + (size_t)b * MK;
    for (int i = t; i < MK; i += 256) row[i] = src[i];
    if (t < IN_F) inp[t] = x[(size_t)b * XCOLS + t];
    __syncthreads();

    if (t < 64) {
        const int o = t;
        float accum = 0.f;
        #pragma unroll
        for (int i = 0; i < IN_F; ++i) {
            const float* g = row + (i * 64 + o) * KF;
            float wsum = ((g[0] + g[1]) + (g[2] + g[3])) + (g[4] + g[5]);
            accum = fmaf(inp[i], wsum, accum);
        }
        const float* g = row + (1024 + o) * KF;
        accum += ((g[0] + g[1]) + (g[2] + g[3])) + (g[4] + g[5]);
        out[(size_t)b * 64 + o] = accum;
    }
}

// ----------------------------- launch ---------------------------------------
extern "C" void kernel_launch(void* const* d_in, const int* in_sizes, int n_in,
                              void* d_out, int out_size)
{
    const float* x  = (const float*)d_in[0];
    const float* W1 = (const float*)d_in[1];
    const float* b1 = (const float*)d_in[2];
    const float* W2 = (const float*)d_in[3];
    const float* b2 = (const float*)d_in[4];
    const float* W3 = (const float*)d_in[5];
    const float* b3 = (const float*)d_in[6];
    float* out = (float*)d_out;

    float *h1, *h2, *cc, *v;
    cudaGetSymbolAddress((void**)&h1, g_h1);
    cudaGetSymbolAddress((void**)&h2, g_h2);
    cudaGetSymbolAddress((void**)&cc, g_cc);
    cudaGetSymbolAddress((void**)&v,  g_v);

    // 1) h1 = tanh(z @ W1 + b1)   z = x[:, 17:145], lda = 145
    sgemm_k<<<dim3(HID / BN, B_SZ / BM), 256>>>(
        x + (IN_F + 1), XCOLS, W1, HID, b1, nullptr, h1, HID,
        HID, LAT, /*mode=*/1);

    // 2) h2 = tanh(h1 @ W2 + b2)
    sgemm_k<<<dim3((CS + BN - 1) / BN, B_SZ / BM), 256>>>(
        h1, HID, W2, CS, b2, nullptr, h2, CS,
        CS, HID, /*mode=*/1);

    // 3) tail 12 columns -> v[b, 0..5]
    tail_v_kernel<<<B_SZ, 128>>>(h2, W3, b3, x, v);

    // 4) big GEMM: cc[b,n] = (h2[b]·W3[:,n] + b3[n]) * v[b, n%6], n < 6528
    sgemm_k<<<dim3(MK / BN, B_SZ / BM), 256>>>(
        h2, CS, W3, CS, b3, v, cc, MK,
        MK, CS, /*mode=*/2);

    // 5) fused group-of-6 sum + adaptive 16->64 linear
    final_kernel<<<B_SZ, 256>>>(cc, x, out);
}